// round 9
// baseline (speedup 1.0000x reference)
#include <cuda_runtime.h>
#include <cuda_fp16.h>
#include <cstdint>

#define DEV __device__ __forceinline__

// -------------------- problem sizes --------------------
static constexpr int BATCH = 4096;
static constexpr int ORULE = 256;
static constexpr int DIM   = 256;

static constexpr int M_TILE  = 128;   // batch rows per CTA
static constexpr int K_CHUNK = 32;    // K slice per pipeline stage
static constexpr int NCHUNK  = DIM / K_CHUNK;  // 8
static constexpr int THREADS = 256;

// -------------------- smem layout (dynamic, byte offsets) --------------------
// rows padded to 40 halves (80B) -> conflict-free ldmatrix with 8-row matrices
static constexpr int XROWB  = 80;                 // bytes per smem row
static constexpr int XBUFB  = M_TILE * XROWB;     // 10240 B  (128 rows)
static constexpr int ABUFB  = DIM * XROWB;        // 20480 B  (256 rows)
static constexpr int OFF_X  = 0;                  // 2 bufs -> 20480
static constexpr int OFF_A  = 2 * XBUFB;          // 20480; 2 bufs -> 40960
static constexpr int OFF_C  = OFF_A + 2 * ABUFB;  // 61440: 256 floats
static constexpr int OFF_P  = OFF_C + 1024;       // 62464: 128x4 floats
static constexpr int SMEM_TOTAL = OFF_P + 2048;   // 64512 B

// -------------------- scratch (device globals; no allocation) --------------------
__device__ __align__(16) __half g_Af[(size_t)ORULE * DIM * DIM];  // 33.5 MB
__device__ __align__(16) __half g_xf[(size_t)BATCH * DIM];        // 2 MB

// -------------------- PTX helpers (all plain-sm_80+ features) --------------------
DEV uint32_t smem_to_u32(const void* p) {
    uint32_t a;
    asm("{ .reg .u64 t; cvta.to.shared.u64 t, %1; cvt.u32.u64 %0, t; }" : "=r"(a) : "l"(p));
    return a;
}

DEV void cp_async16(uint32_t saddr, const void* g) {
    asm volatile("cp.async.cg.shared.global [%0], [%1], 16;" :: "r"(saddr), "l"(g));
}
#define CP_COMMIT() asm volatile("cp.async.commit_group;" ::: "memory")
#define CP_WAIT(n)  asm volatile("cp.async.wait_group %0;" :: "n"(n) : "memory")

#define LDMX4(r0, r1, r2, r3, addr) \
    asm volatile("ldmatrix.sync.aligned.m8n8.x4.shared.b16 {%0,%1,%2,%3}, [%4];" \
                 : "=r"(r0), "=r"(r1), "=r"(r2), "=r"(r3) : "r"(addr))

DEV void mma16816(float* d, const uint32_t* a, uint32_t b0, uint32_t b1) {
    asm volatile(
        "mma.sync.aligned.m16n8k16.row.col.f32.f16.f16.f32 "
        "{%0,%1,%2,%3}, {%4,%5,%6,%7}, {%8,%9}, {%0,%1,%2,%3};"
        : "+f"(d[0]), "+f"(d[1]), "+f"(d[2]), "+f"(d[3])
        : "r"(a[0]), "r"(a[1]), "r"(a[2]), "r"(a[3]), "r"(b0), "r"(b1));
}

// -------------------- prepass: x -> fp16 --------------------
__global__ void build_x_kernel(const float* __restrict__ x) {
    int i = blockIdx.x * 256 + threadIdx.x;
    g_xf[i] = __float2half(x[i]);
}

// -------- prepass: A = triu(rots,1)+triu^T+diag(scales) -> fp16, [o][row][col] ------
// grid.x enumerates 32x32 tile pairs (bi<=bj) of the 8x8 tile grid; grid.y = o
__global__ void build_A_kernel(const float* __restrict__ scales,
                               const float* __restrict__ rots) {
    __shared__ float Us[32][33];
    int o = blockIdx.y;
    int t = blockIdx.x;
    int bi = 0;
    while (t >= 8 - bi) { t -= 8 - bi; bi++; }
    int bj = bi + t;
    int c = threadIdx.x, r = threadIdx.y;

    size_t base = (size_t)o * DIM * DIM;
    Us[r][c] = rots[base + (size_t)(bi * 32 + r) * DIM + (bj * 32 + c)];
    __syncthreads();

    float val;
    if (bi == bj) {
        if (r == c)      val = scales[o * DIM + bi * 32 + r];
        else if (r < c)  val = Us[r][c];
        else             val = Us[c][r];
    } else {
        val = Us[r][c];
    }
    g_Af[base + (size_t)(bi * 32 + r) * DIM + (bj * 32 + c)] = __float2half(val);

    if (bi != bj) {  // mirrored lower tile: A[j][i] = rots[i][j] for i<j
        g_Af[base + (size_t)(bj * 32 + r) * DIM + (bi * 32 + c)] =
            __float2half(Us[c][r]);
    }
}

// -------------------- main kernel: HMMA GEMM + bell epilogue --------------------
__global__ void __launch_bounds__(THREADS, 1)
fuzzy_bell_kernel(const float* __restrict__ centroids,
                  const float* __restrict__ bvec,
                  float* __restrict__ out) {
    extern __shared__ char smem[];
    const uint32_t sb = smem_to_u32(smem);
    const int tid = threadIdx.x;
    const int wid = tid >> 5;
    const int l   = tid & 31;
    const int m0  = blockIdx.x * M_TILE;
    const int o   = blockIdx.y;

    const int wm = wid >> 2;   // 0..1: M half (64 rows)
    const int wn = wid & 3;    // 0..3: N quarter (64 cols)

    float* c_sm = reinterpret_cast<float*>(smem + OFF_C);
    float* part = reinterpret_cast<float*>(smem + OFF_P);
    c_sm[tid] = centroids[o * DIM + tid];

    const __half* Ab = g_Af + ((size_t)o << 16);
    const __half* Xb = g_xf + ((size_t)m0 << 8);

    // ---- issue chunk 0 loads ----
    {
        #pragma unroll
        for (int i = tid; i < 512; i += THREADS) {        // X: 128 rows x 32 halves
            int row = i >> 2, seg = i & 3;
            cp_async16(sb + OFF_X + row * XROWB + seg * 16,
                       Xb + ((size_t)row << 8) + seg * 8);
        }
        #pragma unroll
        for (int i = tid; i < 1024; i += THREADS) {       // A: 256 rows x 32 halves
            int row = i >> 2, seg = i & 3;
            cp_async16(sb + OFF_A + row * XROWB + seg * 16,
                       Ab + ((size_t)row << 8) + seg * 8);
        }
        CP_COMMIT();
    }

    float d[4][8][4] = {};   // 128 fp32 accumulators: 4 m16-tiles x 8 n8-tiles

    for (int kt = 0; kt < NCHUNK; kt++) {
        const int buf = kt & 1;
        if (kt < NCHUNK - 1) {  // prefetch next chunk into other buffer
            const int nb = (kt + 1) & 1;
            const int k0 = (kt + 1) * K_CHUNK;
            #pragma unroll
            for (int i = tid; i < 512; i += THREADS) {
                int row = i >> 2, seg = i & 3;
                cp_async16(sb + OFF_X + nb * XBUFB + row * XROWB + seg * 16,
                           Xb + ((size_t)row << 8) + k0 + seg * 8);
            }
            #pragma unroll
            for (int i = tid; i < 1024; i += THREADS) {
                int row = i >> 2, seg = i & 3;
                cp_async16(sb + OFF_A + nb * ABUFB + row * XROWB + seg * 16,
                           Ab + ((size_t)row << 8) + k0 + seg * 8);
            }
            CP_COMMIT();
            CP_WAIT(1);
        } else {
            CP_WAIT(0);
        }
        __syncthreads();

        const uint32_t xbase = sb + OFF_X + buf * XBUFB;
        const uint32_t abase = sb + OFF_A + buf * ABUFB;

        #pragma unroll
        for (int kk = 0; kk < 2; kk++) {   // two k16 steps per chunk
            uint32_t xf[4][4], bf[4][4];
            #pragma unroll
            for (int mt = 0; mt < 4; mt++) {   // X (A-operand) m16k16 frags
                uint32_t addr = xbase + (64 * wm + 16 * mt + (l & 15)) * XROWB
                              + kk * 32 + (l >> 4) * 16;
                LDMX4(xf[mt][0], xf[mt][1], xf[mt][2], xf[mt][3], addr);
            }
            #pragma unroll
            for (int nt = 0; nt < 4; nt++) {   // A (B-operand) 2x n8k16 frags
                int mg = l >> 3, r = l & 7;
                uint32_t addr = abase
                              + (64 * wn + 16 * nt + ((mg >> 1) << 3) + r) * XROWB
                              + kk * 32 + (mg & 1) * 16;
                LDMX4(bf[nt][0], bf[nt][1], bf[nt][2], bf[nt][3], addr);
            }
            #pragma unroll
            for (int mt = 0; mt < 4; mt++)
                #pragma unroll
                for (int n8 = 0; n8 < 8; n8++)
                    mma16816(d[mt][n8], xf[mt],
                             bf[n8 >> 1][(n8 & 1) * 2],
                             bf[n8 >> 1][(n8 & 1) * 2 + 1]);
        }
        __syncthreads();
    }

    // ---- epilogue: y += centroid, row-squared-sum, bell membership ----
    #pragma unroll
    for (int mt = 0; mt < 4; mt++) {
        #pragma unroll
        for (int h = 0; h < 2; h++) {  // row halves within m16 tile
            float s = 0.0f;
            #pragma unroll
            for (int n8 = 0; n8 < 8; n8++) {
                int n = 64 * wn + 8 * n8 + ((l & 3) << 1);
                float v0 = d[mt][n8][h * 2]     + c_sm[n];
                float v1 = d[mt][n8][h * 2 + 1] + c_sm[n + 1];
                s = fmaf(v0, v0, fmaf(v1, v1, s));
            }
            s += __shfl_xor_sync(0xffffffffu, s, 1);
            s += __shfl_xor_sync(0xffffffffu, s, 2);
            if ((l & 3) == 0)
                part[(64 * wm + 16 * mt + 8 * h + (l >> 2)) * 4 + wn] = s;
        }
    }
    __syncthreads();

    if (tid < 128) {
        float acc = part[tid * 4] + part[tid * 4 + 1]
                  + part[tid * 4 + 2] + part[tid * 4 + 3];
        float bb = bvec[o];
        float p = exp2f(bb * log2f(acc));   // (rx^2)^b = rx^(2b)
        out[(size_t)(m0 + tid) * ORULE + o] = 1.0f / (1.0f + p);
    }
}

// -------------------- launch --------------------
extern "C" void kernel_launch(void* const* d_in, const int* in_sizes, int n_in,
                              void* d_out, int out_size) {
    (void)in_sizes; (void)n_in; (void)out_size;
    const float* x         = (const float*)d_in[0];   // [4096,256]
    const float* scales    = (const float*)d_in[1];   // [256,256]
    const float* rots      = (const float*)d_in[2];   // [256,256,256]
    const float* centroids = (const float*)d_in[3];   // [256,256,1]
    const float* bvec      = (const float*)d_in[4];   // [256]
    float* out = (float*)d_out;                       // [4096,256]

    cudaFuncSetAttribute(fuzzy_bell_kernel,
                         cudaFuncAttributeMaxDynamicSharedMemorySize, SMEM_TOTAL);

    build_x_kernel<<<BATCH, 256>>>(x);
    build_A_kernel<<<dim3(36, ORULE), dim3(32, 32)>>>(scales, rots);
    fuzzy_bell_kernel<<<dim3(BATCH / M_TILE, ORULE), THREADS, SMEM_TOTAL>>>(
        centroids, bvec, out);
}

// round 10
// speedup vs baseline: 1.2374x; 1.2374x over previous
#include <cuda_runtime.h>
#include <cuda_fp16.h>
#include <cstdint>

#define DEV __device__ __forceinline__

// -------------------- problem sizes --------------------
static constexpr int BATCH = 4096;
static constexpr int ORULE = 256;
static constexpr int DIM   = 256;

static constexpr int M_TILE  = 128;   // batch rows per CTA
static constexpr int K_CHUNK = 64;    // K slice per pipeline stage
static constexpr int NCHUNK  = DIM / K_CHUNK;  // 4
static constexpr int STAGES  = 3;
static constexpr int THREADS = 512;   // 16 warps, 4 per SMSP

// -------------------- smem layout --------------------
// rows padded to 72 halves (144B): 8-row ldmatrix stride 144B -> 36 words -> distinct banks
static constexpr int ROWB   = 144;                 // bytes per smem row (64 halves + pad)
static constexpr int XBUFB  = M_TILE * ROWB;       // 18432
static constexpr int ABUFB  = DIM * ROWB;          // 36864
static constexpr int OFF_XS = 0;
static constexpr int OFF_AS = XBUFB;
static constexpr int STAGE_BYTES = XBUFB + ABUFB;  // 55296
static constexpr int OFF_C  = STAGES * STAGE_BYTES;        // 165888 (256 floats)
static constexpr int OFF_P  = OFF_C + 1024;                // 166912 (128x4 floats)
static constexpr int SMEM_TOTAL = OFF_P + 2048;            // 168960

// -------------------- scratch (device globals; no allocation) --------------------
__device__ __align__(16) __half g_Af[(size_t)ORULE * DIM * DIM];  // 33.5 MB
__device__ __align__(16) __half g_xf[(size_t)BATCH * DIM];        // 2 MB

// -------------------- PTX helpers (sm_80-era, compiles at compute_103) ----------
DEV uint32_t smem_to_u32(const void* p) {
    uint32_t a;
    asm("{ .reg .u64 t; cvta.to.shared.u64 t, %1; cvt.u32.u64 %0, t; }" : "=r"(a) : "l"(p));
    return a;
}

DEV void cp_async16(uint32_t saddr, const void* g) {
    asm volatile("cp.async.cg.shared.global [%0], [%1], 16;" :: "r"(saddr), "l"(g));
}
#define CP_COMMIT() asm volatile("cp.async.commit_group;" ::: "memory")
#define CP_WAIT(n)  asm volatile("cp.async.wait_group %0;" :: "n"(n) : "memory")

#define LDMX4(r0, r1, r2, r3, addr) \
    asm volatile("ldmatrix.sync.aligned.m8n8.x4.shared.b16 {%0,%1,%2,%3}, [%4];" \
                 : "=r"(r0), "=r"(r1), "=r"(r2), "=r"(r3) : "r"(addr))

DEV void mma16816(float* d, const uint32_t* a, uint32_t b0, uint32_t b1) {
    asm volatile(
        "mma.sync.aligned.m16n8k16.row.col.f32.f16.f16.f32 "
        "{%0,%1,%2,%3}, {%4,%5,%6,%7}, {%8,%9}, {%0,%1,%2,%3};"
        : "+f"(d[0]), "+f"(d[1]), "+f"(d[2]), "+f"(d[3])
        : "r"(a[0]), "r"(a[1]), "r"(a[2]), "r"(a[3]), "r"(b0), "r"(b1));
}

// -------------------- prepass: x -> fp16 --------------------
__global__ void build_x_kernel(const float* __restrict__ x) {
    int i = blockIdx.x * 256 + threadIdx.x;
    g_xf[i] = __float2half(x[i]);
}

// -------- prepass: A = triu(rots,1)+triu^T+diag(scales) -> fp16, [o][row][col] ------
__global__ void build_A_kernel(const float* __restrict__ scales,
                               const float* __restrict__ rots) {
    __shared__ float Us[32][33];
    int o = blockIdx.y;
    int t = blockIdx.x;
    int bi = 0;
    while (t >= 8 - bi) { t -= 8 - bi; bi++; }
    int bj = bi + t;
    int c = threadIdx.x, r = threadIdx.y;

    size_t base = (size_t)o * DIM * DIM;
    Us[r][c] = rots[base + (size_t)(bi * 32 + r) * DIM + (bj * 32 + c)];
    __syncthreads();

    float val;
    if (bi == bj) {
        if (r == c)      val = scales[o * DIM + bi * 32 + r];
        else if (r < c)  val = Us[r][c];
        else             val = Us[c][r];
    } else {
        val = Us[r][c];
    }
    g_Af[base + (size_t)(bi * 32 + r) * DIM + (bj * 32 + c)] = __float2half(val);

    if (bi != bj) {  // mirrored lower tile: A[j][i] = rots[i][j] for i<j
        g_Af[base + (size_t)(bj * 32 + r) * DIM + (bi * 32 + c)] =
            __float2half(Us[c][r]);
    }
}

// -------------------- chunk loader: one K_CHUNK slice of X and A --------------------
DEV void issue_chunk(uint32_t sb, int tid, const __half* __restrict__ Xb,
                     const __half* __restrict__ Ab, int stage, int k0) {
    const uint32_t base = sb + stage * STAGE_BYTES;
    #pragma unroll
    for (int i = tid; i < 1024; i += THREADS) {      // X: 128 rows x 64 halves
        int row = i >> 3, seg = i & 7;
        cp_async16(base + OFF_XS + row * ROWB + seg * 16,
                   Xb + ((size_t)row << 8) + k0 + seg * 8);
    }
    #pragma unroll
    for (int i = tid; i < 2048; i += THREADS) {      // A: 256 rows x 64 halves
        int row = i >> 3, seg = i & 7;
        cp_async16(base + OFF_AS + row * ROWB + seg * 16,
                   Ab + ((size_t)row << 8) + k0 + seg * 8);
    }
}

// -------------------- main kernel: HMMA GEMM + bell epilogue --------------------
__global__ void __launch_bounds__(THREADS, 1)
fuzzy_bell_kernel(const float* __restrict__ centroids,
                  const float* __restrict__ bvec,
                  float* __restrict__ out) {
    extern __shared__ char smem[];
    const uint32_t sb = smem_to_u32(smem);
    const int tid = threadIdx.x;
    const int wid = tid >> 5;
    const int l   = tid & 31;
    const int m0  = blockIdx.x * M_TILE;
    const int o   = blockIdx.y;

    const int wmi = wid >> 2;   // 0..3: M group (32 rows)
    const int wn  = wid & 3;    // 0..3: N quarter (64 cols)

    float* c_sm = reinterpret_cast<float*>(smem + OFF_C);
    float* part = reinterpret_cast<float*>(smem + OFF_P);
    if (tid < 256) c_sm[tid] = centroids[o * DIM + tid];

    const __half* Ab = g_Af + ((size_t)o << 16);
    const __half* Xb = g_xf + ((size_t)m0 << 8);

    // prologue: stages 0,1 in flight
    issue_chunk(sb, tid, Xb, Ab, 0, 0);
    CP_COMMIT();
    issue_chunk(sb, tid, Xb, Ab, 1, K_CHUNK);
    CP_COMMIT();

    float d[2][8][4] = {};   // 64 fp32 accumulators: 2 m16-tiles x 8 n8-tiles

    const int mg = l >> 3, rr = l & 7;   // for B-operand ldmatrix addressing

    #pragma unroll
    for (int kt = 0; kt < NCHUNK; kt++) {
        if (kt < NCHUNK - 1) { CP_WAIT(1); } else { CP_WAIT(0); }
        __syncthreads();
        // stage (kt+2)%3 == stage (kt-1)%3: freed by compute(kt-1) before this sync
        if (kt + 2 < NCHUNK) {
            issue_chunk(sb, tid, Xb, Ab, (kt + 2) % STAGES, (kt + 2) * K_CHUNK);
            CP_COMMIT();
        }

        const uint32_t xbase = sb + (kt % STAGES) * STAGE_BYTES + OFF_XS;
        const uint32_t abase = sb + (kt % STAGES) * STAGE_BYTES + OFF_AS;

        #pragma unroll
        for (int kk = 0; kk < K_CHUNK / 16; kk++) {
            uint32_t xf[2][4], bf[4][4];
            #pragma unroll
            for (int mt = 0; mt < 2; mt++) {   // X (A-operand) m16k16 frags
                uint32_t addr = xbase + (32 * wmi + 16 * mt + (l & 15)) * ROWB
                              + kk * 32 + (l >> 4) * 16;
                LDMX4(xf[mt][0], xf[mt][1], xf[mt][2], xf[mt][3], addr);
            }
            #pragma unroll
            for (int nt = 0; nt < 4; nt++) {   // A (B-operand) 2x n8k16 frags
                uint32_t addr = abase
                              + (64 * wn + 16 * nt + ((mg >> 1) << 3) + rr) * ROWB
                              + kk * 32 + (mg & 1) * 16;
                LDMX4(bf[nt][0], bf[nt][1], bf[nt][2], bf[nt][3], addr);
            }
            #pragma unroll
            for (int mt = 0; mt < 2; mt++)
                #pragma unroll
                for (int n8 = 0; n8 < 8; n8++)
                    mma16816(d[mt][n8], xf[mt],
                             bf[n8 >> 1][(n8 & 1) * 2],
                             bf[n8 >> 1][(n8 & 1) * 2 + 1]);
        }
    }
    __syncthreads();

    // ---- epilogue: y += centroid, row-squared-sum, bell membership ----
    #pragma unroll
    for (int mt = 0; mt < 2; mt++) {
        #pragma unroll
        for (int h = 0; h < 2; h++) {  // row halves within m16 tile
            float s = 0.0f;
            #pragma unroll
            for (int n8 = 0; n8 < 8; n8++) {
                int n = 64 * wn + 8 * n8 + ((l & 3) << 1);
                float v0 = d[mt][n8][h * 2]     + c_sm[n];
                float v1 = d[mt][n8][h * 2 + 1] + c_sm[n + 1];
                s = fmaf(v0, v0, fmaf(v1, v1, s));
            }
            s += __shfl_xor_sync(0xffffffffu, s, 1);
            s += __shfl_xor_sync(0xffffffffu, s, 2);
            if ((l & 3) == 0)
                part[(32 * wmi + 16 * mt + 8 * h + (l >> 2)) * 4 + wn] = s;
        }
    }
    __syncthreads();

    if (tid < 128) {
        float acc = part[tid * 4] + part[tid * 4 + 1]
                  + part[tid * 4 + 2] + part[tid * 4 + 3];
        float bb = bvec[o];
        float p = exp2f(bb * log2f(acc));   // (rx^2)^b = rx^(2b)
        out[(size_t)(m0 + tid) * ORULE + o] = 1.0f / (1.0f + p);
    }
}

// -------------------- launch --------------------
extern "C" void kernel_launch(void* const* d_in, const int* in_sizes, int n_in,
                              void* d_out, int out_size) {
    (void)in_sizes; (void)n_in; (void)out_size;
    const float* x         = (const float*)d_in[0];   // [4096,256]
    const float* scales    = (const float*)d_in[1];   // [256,256]
    const float* rots      = (const float*)d_in[2];   // [256,256,256]
    const float* centroids = (const float*)d_in[3];   // [256,256,1]
    const float* bvec      = (const float*)d_in[4];   // [256]
    float* out = (float*)d_out;                       // [4096,256]

    cudaFuncSetAttribute(fuzzy_bell_kernel,
                         cudaFuncAttributeMaxDynamicSharedMemorySize, SMEM_TOTAL);

    build_x_kernel<<<BATCH, 256>>>(x);
    build_A_kernel<<<dim3(36, ORULE), dim3(32, 32)>>>(scales, rots);
    fuzzy_bell_kernel<<<dim3(BATCH / M_TILE, ORULE), THREADS, SMEM_TOTAL>>>(
        centroids, bvec, out);
}

// round 12
// speedup vs baseline: 1.2801x; 1.0345x over previous
#include <cuda_runtime.h>
#include <cuda_fp16.h>
#include <cstdint>

#define DEV __device__ __forceinline__

// -------------------- problem sizes --------------------
static constexpr int BATCH = 4096;
static constexpr int ORULE = 256;
static constexpr int DIM   = 256;

static constexpr int M_TILE  = 128;              // batch rows per tile
static constexpr int K_CHUNK = 64;               // K slice per pipeline stage
static constexpr int KT_PER_TILE = DIM / K_CHUNK;  // 4
static constexpr int STAGES  = 3;
static constexpr int THREADS = 512;              // 16 warps, 4 per SMSP
static constexpr int NTILES  = (BATCH / M_TILE) * ORULE;  // 8192, o-major
static constexpr int NSM     = 148;              // sm_103a SM count
static constexpr int TILES_PER_CTA = (NTILES + NSM - 1) / NSM;  // 56
static constexpr int GRID    = (NTILES + TILES_PER_CTA - 1) / TILES_PER_CTA;  // 147

// -------------------- smem layout --------------------
// rows padded to 72 halves (144B): conflict-free ldmatrix (R9/R10-verified)
static constexpr int ROWB   = 144;
static constexpr int XBUFB  = M_TILE * ROWB;       // 18432
static constexpr int ABUFB  = DIM * ROWB;          // 36864
static constexpr int OFF_XS = 0;
static constexpr int OFF_AS = XBUFB;
static constexpr int STAGE_BYTES = XBUFB + ABUFB;  // 55296
static constexpr int OFF_C  = STAGES * STAGE_BYTES;        // 165888: c_sm[2][256] floats
static constexpr int OFF_P  = OFF_C + 2048;                // 167936: 128x4 floats
static constexpr int SMEM_TOTAL = OFF_P + 2048;            // 169984

// -------------------- scratch (device globals; no allocation) --------------------
__device__ __align__(16) __half g_Af[(size_t)ORULE * DIM * DIM];  // 33.5 MB
__device__ __align__(16) __half g_xf[(size_t)BATCH * DIM];        // 2 MB

// -------------------- PTX helpers (sm_80-era, compile at compute_103) ----------
DEV uint32_t smem_to_u32(const void* p) {
    uint32_t a;
    asm("{ .reg .u64 t; cvta.to.shared.u64 t, %1; cvt.u32.u64 %0, t; }" : "=r"(a) : "l"(p));
    return a;
}

DEV void cp_async16(uint32_t saddr, const void* g) {
    asm volatile("cp.async.cg.shared.global [%0], [%1], 16;" :: "r"(saddr), "l"(g));
}
#define CP_COMMIT() asm volatile("cp.async.commit_group;" ::: "memory")
#define CP_WAIT(n)  asm volatile("cp.async.wait_group %0;" :: "n"(n) : "memory")

#define LDMX4(r0, r1, r2, r3, addr) \
    asm volatile("ldmatrix.sync.aligned.m8n8.x4.shared.b16 {%0,%1,%2,%3}, [%4];" \
                 : "=r"(r0), "=r"(r1), "=r"(r2), "=r"(r3) : "r"(addr))

DEV void mma16816(float* d, const uint32_t* a, uint32_t b0, uint32_t b1) {
    asm volatile(
        "mma.sync.aligned.m16n8k16.row.col.f32.f16.f16.f32 "
        "{%0,%1,%2,%3}, {%4,%5,%6,%7}, {%8,%9}, {%0,%1,%2,%3};"
        : "+f"(d[0]), "+f"(d[1]), "+f"(d[2]), "+f"(d[3])
        : "r"(a[0]), "r"(a[1]), "r"(a[2]), "r"(a[3]), "r"(b0), "r"(b1));
}

// -------------------- prepass: x -> fp16 --------------------
__global__ void build_x_kernel(const float* __restrict__ x) {
    int i = blockIdx.x * 256 + threadIdx.x;
    g_xf[i] = __float2half(x[i]);
}

// -------- prepass: A = triu(rots,1)+triu^T+diag(scales) -> fp16, [o][row][col] ------
__global__ void build_A_kernel(const float* __restrict__ scales,
                               const float* __restrict__ rots) {
    __shared__ float Us[32][33];
    int o = blockIdx.y;
    int t = blockIdx.x;
    int bi = 0;
    while (t >= 8 - bi) { t -= 8 - bi; bi++; }
    int bj = bi + t;
    int c = threadIdx.x, r = threadIdx.y;

    size_t base = (size_t)o * DIM * DIM;
    Us[r][c] = rots[base + (size_t)(bi * 32 + r) * DIM + (bj * 32 + c)];
    __syncthreads();

    float val;
    if (bi == bj) {
        if (r == c)      val = scales[o * DIM + bi * 32 + r];
        else if (r < c)  val = Us[r][c];
        else             val = Us[c][r];
    } else {
        val = Us[r][c];
    }
    g_Af[base + (size_t)(bi * 32 + r) * DIM + (bj * 32 + c)] = __float2half(val);

    if (bi != bj) {  // mirrored lower tile: A[j][i] = rots[i][j] for i<j
        g_Af[base + (size_t)(bj * 32 + r) * DIM + (bi * 32 + c)] =
            __float2half(Us[c][r]);
    }
}

// -------------------- chunk loader: chunk c (global index from tile_start) ----------
// tile = tile_start + c/4 (o-major: o = tile>>5, mi = tile&31), kt = c%4, stage = c%3
DEV void issue_chunk(uint32_t sb, int tid, int tile_start, int c) {
    const int tile = tile_start + (c >> 2);
    const int kt   = c & 3;
    const int o    = tile >> 5;
    const int mi   = tile & 31;
    const __half* Xb = g_xf + (((size_t)mi * M_TILE) << 8) + kt * K_CHUNK;
    const __half* Ab = g_Af + ((size_t)o << 16) + kt * K_CHUNK;
    const uint32_t base = sb + (c % STAGES) * STAGE_BYTES;
    #pragma unroll
    for (int i = tid; i < 1024; i += THREADS) {      // X: 128 rows x 64 halves
        int row = i >> 3, seg = i & 7;
        cp_async16(base + OFF_XS + row * ROWB + seg * 16,
                   Xb + ((size_t)row << 8) + seg * 8);
    }
    #pragma unroll
    for (int i = tid; i < 2048; i += THREADS) {      // A: 256 rows x 64 halves
        int row = i >> 3, seg = i & 7;
        cp_async16(base + OFF_AS + row * ROWB + seg * 16,
                   Ab + ((size_t)row << 8) + seg * 8);
    }
}

// -------------------- main kernel: persistent HMMA GEMM + bell epilogue -------------
__global__ void __launch_bounds__(THREADS, 1)
fuzzy_bell_kernel(const float* __restrict__ centroids,
                  const float* __restrict__ bvec,
                  float* __restrict__ out) {
    extern __shared__ char smem[];
    const uint32_t sb = smem_to_u32(smem);
    const int tid = threadIdx.x;
    const int wid = tid >> 5;
    const int l   = tid & 31;

    const int t_start = blockIdx.x * TILES_PER_CTA;
    if (t_start >= NTILES) return;
    const int t_end   = min(t_start + TILES_PER_CTA, NTILES);
    const int nchunks = (t_end - t_start) * KT_PER_TILE;

    const int wmi = wid >> 2;   // 0..3: M group (32 rows)
    const int wn  = wid & 3;    // 0..3: N quarter (64 cols)
    const int mg  = l >> 3, rr = l & 7;

    float* c_sm = reinterpret_cast<float*>(smem + OFF_C);   // [2][256]
    float* part = reinterpret_cast<float*>(smem + OFF_P);

    // prologue: 2 chunks in flight
    issue_chunk(sb, tid, t_start, 0);
    CP_COMMIT();
    if (nchunks > 1) {
        issue_chunk(sb, tid, t_start, 1);
        CP_COMMIT();
    }

    for (int tile = t_start; tile < t_end; tile++) {
        const int o  = tile >> 5;
        const int m0 = (tile & 31) * M_TILE;
        const int pr = tile & 1;

        float d[2][8][4];
        #pragma unroll
        for (int a = 0; a < 2; a++)
            #pragma unroll
            for (int bq = 0; bq < 8; bq++)
                #pragma unroll
                for (int cq = 0; cq < 4; cq++) d[a][bq][cq] = 0.0f;

        #pragma unroll
        for (int kt = 0; kt < KT_PER_TILE; kt++) {
            const int c = (tile - t_start) * KT_PER_TILE + kt;
            if (c == nchunks - 1) { CP_WAIT(0); } else { CP_WAIT(1); }
            __syncthreads();

            if (kt == 0 && tid < 256)
                c_sm[pr * 256 + tid] = centroids[o * DIM + tid];

            if (c + 2 < nchunks) {
                issue_chunk(sb, tid, t_start, c + 2);
                CP_COMMIT();
            }

            const uint32_t xbase = sb + (c % STAGES) * STAGE_BYTES + OFF_XS;
            const uint32_t abase = sb + (c % STAGES) * STAGE_BYTES + OFF_AS;

            #pragma unroll
            for (int kk = 0; kk < K_CHUNK / 16; kk++) {
                uint32_t xf[2][4], bf[4][4];
                #pragma unroll
                for (int mt = 0; mt < 2; mt++) {   // X (A-operand) m16k16 frags
                    uint32_t addr = xbase + (32 * wmi + 16 * mt + (l & 15)) * ROWB
                                  + kk * 32 + (l >> 4) * 16;
                    LDMX4(xf[mt][0], xf[mt][1], xf[mt][2], xf[mt][3], addr);
                }
                #pragma unroll
                for (int nt = 0; nt < 4; nt++) {   // A (B-operand) 2x n8k16 frags
                    uint32_t addr = abase
                                  + (64 * wn + 16 * nt + ((mg >> 1) << 3) + rr) * ROWB
                                  + kk * 32 + (mg & 1) * 16;
                    LDMX4(bf[nt][0], bf[nt][1], bf[nt][2], bf[nt][3], addr);
                }
                #pragma unroll
                for (int mt = 0; mt < 2; mt++)
                    #pragma unroll
                    for (int n8 = 0; n8 < 8; n8++)
                        mma16816(d[mt][n8], xf[mt],
                                 bf[n8 >> 1][(n8 & 1) * 2],
                                 bf[n8 >> 1][(n8 & 1) * 2 + 1]);
            }
        }

        // ---- epilogue: y += centroid, row-squared-sum, bell membership ----
        #pragma unroll
        for (int mt = 0; mt < 2; mt++) {
            #pragma unroll
            for (int h = 0; h < 2; h++) {
                float s = 0.0f;
                #pragma unroll
                for (int n8 = 0; n8 < 8; n8++) {
                    int n = 64 * wn + 8 * n8 + ((l & 3) << 1);
                    float v0 = d[mt][n8][h * 2]     + c_sm[pr * 256 + n];
                    float v1 = d[mt][n8][h * 2 + 1] + c_sm[pr * 256 + n + 1];
                    s = fmaf(v0, v0, fmaf(v1, v1, s));
                }
                s += __shfl_xor_sync(0xffffffffu, s, 1);
                s += __shfl_xor_sync(0xffffffffu, s, 2);
                if ((l & 3) == 0)
                    part[(32 * wmi + 16 * mt + 8 * h + (l >> 2)) * 4 + wn] = s;
            }
        }
        __syncthreads();

        if (tid < 128) {
            float acc = part[tid * 4] + part[tid * 4 + 1]
                      + part[tid * 4 + 2] + part[tid * 4 + 3];
            float bb = __ldg(bvec + o);
            float p = exp2f(bb * log2f(acc));   // (rx^2)^b = rx^(2b)
            out[(size_t)(m0 + tid) * ORULE + o] = 1.0f / (1.0f + p);
        }
        // next tile's first CP_WAIT+__syncthreads orders 'part' reuse;
        // c_sm is parity double-buffered
        __syncthreads();
    }
}

// -------------------- launch --------------------
extern "C" void kernel_launch(void* const* d_in, const int* in_sizes, int n_in,
                              void* d_out, int out_size) {
    (void)in_sizes; (void)n_in; (void)out_size;
    const float* x         = (const float*)d_in[0];   // [4096,256]
    const float* scales    = (const float*)d_in[1];   // [256,256]
    const float* rots      = (const float*)d_in[2];   // [256,256,256]
    const float* centroids = (const float*)d_in[3];   // [256,256,1]
    const float* bvec      = (const float*)d_in[4];   // [256]
    float* out = (float*)d_out;                       // [4096,256]

    cudaFuncSetAttribute(fuzzy_bell_kernel,
                         cudaFuncAttributeMaxDynamicSharedMemorySize, SMEM_TOTAL);

    build_x_kernel<<<BATCH, 256>>>(x);
    build_A_kernel<<<dim3(36, ORULE), dim3(32, 32)>>>(scales, rots);
    fuzzy_bell_kernel<<<GRID, THREADS, SMEM_TOTAL>>>(centroids, bvec, out);
}

// round 13
// speedup vs baseline: 1.4446x; 1.1285x over previous
#include <cuda_runtime.h>
#include <cuda_fp16.h>
#include <cstdint>

#define DEV __device__ __forceinline__

// -------------------- problem sizes --------------------
static constexpr int BATCH = 4096;
static constexpr int ORULE = 256;
static constexpr int DIM   = 256;

static constexpr int M_TILE  = 128;                // batch rows per tile
static constexpr int K_CHUNK = 64;                 // K slice per X pipeline stage
static constexpr int KT_PER_TILE = DIM / K_CHUNK;  // 4
static constexpr int STAGES  = 3;                  // X ring stages
static constexpr int THREADS = 512;                // 16 warps, 4 per SMSP
static constexpr int NTILES  = (BATCH / M_TILE) * ORULE;  // 8192, o-major
static constexpr int NSM     = 148;
static constexpr int TILES_PER_CTA = (NTILES + NSM - 1) / NSM;  // 56
static constexpr int GRID    = (NTILES + TILES_PER_CTA - 1) / TILES_PER_CTA;

// -------------------- smem layout --------------------
// rows padded to 72 halves (144B): conflict-free ldmatrix (R9-verified)
static constexpr int ROWB   = 144;
static constexpr int XBUFB  = M_TILE * ROWB;       // 18432: one X stage
static constexpr int ABUFB  = DIM * ROWB;          // 36864: one A K-chunk
static constexpr int OFF_X  = 0;                   // 3 stages -> 55296
static constexpr int OFF_A  = STAGES * XBUFB;      // 55296; 4 chunks -> 147456
static constexpr int OFF_C  = OFF_A + KT_PER_TILE * ABUFB;  // 202752: c_sm[2][256]
static constexpr int OFF_P  = OFF_C + 2048;                 // 204800: 128x4 floats
static constexpr int SMEM_TOTAL = OFF_P + 2048;             // 206848

// -------------------- scratch (device globals; no allocation) --------------------
__device__ __align__(16) __half g_Af[(size_t)ORULE * DIM * DIM];  // 33.5 MB
__device__ __align__(16) __half g_xf[(size_t)BATCH * DIM];        // 2 MB

// -------------------- PTX helpers (sm_80-era, compile at compute_103) ----------
DEV uint32_t smem_to_u32(const void* p) {
    uint32_t a;
    asm("{ .reg .u64 t; cvta.to.shared.u64 t, %1; cvt.u32.u64 %0, t; }" : "=r"(a) : "l"(p));
    return a;
}

DEV void cp_async16(uint32_t saddr, const void* g) {
    asm volatile("cp.async.cg.shared.global [%0], [%1], 16;" :: "r"(saddr), "l"(g));
}
#define CP_COMMIT() asm volatile("cp.async.commit_group;" ::: "memory")
#define CP_WAIT(n)  asm volatile("cp.async.wait_group %0;" :: "n"(n) : "memory")

#define LDMX4(r0, r1, r2, r3, addr) \
    asm volatile("ldmatrix.sync.aligned.m8n8.x4.shared.b16 {%0,%1,%2,%3}, [%4];" \
                 : "=r"(r0), "=r"(r1), "=r"(r2), "=r"(r3) : "r"(addr))

DEV void mma16816(float* d, const uint32_t* a, uint32_t b0, uint32_t b1) {
    asm volatile(
        "mma.sync.aligned.m16n8k16.row.col.f32.f16.f16.f32 "
        "{%0,%1,%2,%3}, {%4,%5,%6,%7}, {%8,%9}, {%0,%1,%2,%3};"
        : "+f"(d[0]), "+f"(d[1]), "+f"(d[2]), "+f"(d[3])
        : "r"(a[0]), "r"(a[1]), "r"(a[2]), "r"(a[3]), "r"(b0), "r"(b1));
}

// -------------------- prepass: x -> fp16 --------------------
__global__ void build_x_kernel(const float* __restrict__ x) {
    int i = blockIdx.x * 256 + threadIdx.x;
    g_xf[i] = __float2half(x[i]);
}

// -------- prepass: A = triu(rots,1)+triu^T+diag(scales) -> fp16, [o][row][col] ------
__global__ void build_A_kernel(const float* __restrict__ scales,
                               const float* __restrict__ rots) {
    __shared__ float Us[32][33];
    int o = blockIdx.y;
    int t = blockIdx.x;
    int bi = 0;
    while (t >= 8 - bi) { t -= 8 - bi; bi++; }
    int bj = bi + t;
    int c = threadIdx.x, r = threadIdx.y;

    size_t base = (size_t)o * DIM * DIM;
    Us[r][c] = rots[base + (size_t)(bi * 32 + r) * DIM + (bj * 32 + c)];
    __syncthreads();

    float val;
    if (bi == bj) {
        if (r == c)      val = scales[o * DIM + bi * 32 + r];
        else if (r < c)  val = Us[r][c];
        else             val = Us[c][r];
    } else {
        val = Us[r][c];
    }
    g_Af[base + (size_t)(bi * 32 + r) * DIM + (bj * 32 + c)] = __float2half(val);

    if (bi != bj) {  // mirrored lower tile: A[j][i] = rots[i][j] for i<j
        g_Af[base + (size_t)(bj * 32 + r) * DIM + (bi * 32 + c)] =
            __float2half(Us[c][r]);
    }
}

// -------------------- loaders --------------------
// X chunk c (counted within the current o-run): tile = run_tile0 + c/4, kt = c%4
DEV void issue_x_chunk(uint32_t sb, int tid, int run_tile0, int c) {
    const int tile = run_tile0 + (c >> 2);
    const int kt   = c & 3;
    const int mi   = tile & 31;
    const __half* Xb = g_xf + (((size_t)mi * M_TILE) << 8) + kt * K_CHUNK;
    const uint32_t base = sb + OFF_X + (c % STAGES) * XBUFB;
    #pragma unroll
    for (int i = tid; i < 1024; i += THREADS) {      // 128 rows x 64 halves
        int row = i >> 3, seg = i & 7;
        cp_async16(base + row * ROWB + seg * 16,
                   Xb + ((size_t)row << 8) + seg * 8);
    }
}

// full A[o]: 4 K-chunks, 256 rows x 64 halves each
DEV void issue_A(uint32_t sb, int tid, int o) {
    const __half* Ao = g_Af + ((size_t)o << 16);
    #pragma unroll
    for (int kt = 0; kt < KT_PER_TILE; kt++) {
        const uint32_t base = sb + OFF_A + kt * ABUFB;
        const __half* Ab = Ao + kt * K_CHUNK;
        for (int i = tid; i < 2048; i += THREADS) {
            int row = i >> 3, seg = i & 7;
            cp_async16(base + row * ROWB + seg * 16,
                       Ab + ((size_t)row << 8) + seg * 8);
        }
    }
}

// -------------------- main kernel: persistent, A smem-resident per o-run ------------
__global__ void __launch_bounds__(THREADS, 1)
fuzzy_bell_kernel(const float* __restrict__ centroids,
                  const float* __restrict__ bvec,
                  float* __restrict__ out) {
    extern __shared__ char smem[];
    const uint32_t sb = smem_to_u32(smem);
    const int tid = threadIdx.x;
    const int wid = tid >> 5;
    const int l   = tid & 31;

    const int t_start = blockIdx.x * TILES_PER_CTA;
    if (t_start >= NTILES) return;
    const int t_end = min(t_start + TILES_PER_CTA, NTILES);

    const int wmi = wid >> 2;   // 0..3: M group (32 rows)
    const int wn  = wid & 3;    // 0..3: N quarter (64 cols)
    const int mg  = l >> 3, rr = l & 7;

    float* c_sm = reinterpret_cast<float*>(smem + OFF_C);   // [2][256]
    float* part = reinterpret_cast<float*>(smem + OFF_P);

    int tile = t_start;
    while (tile < t_end) {
        const int o    = tile >> 5;
        const int gend = min(t_end, (o + 1) << 5);   // end of this o-run
        const int run0 = tile;
        const int nchunks = (gend - run0) * KT_PER_TILE;

        // ---- o-boundary: drain ring, load A[o] + prologue X chunks ----
        CP_WAIT(0);
        __syncthreads();            // all compute on previous A finished (serial)
        issue_A(sb, tid, o);
        CP_COMMIT();                                   // group [A]
        issue_x_chunk(sb, tid, run0, 0);
        CP_COMMIT();                                   // group [X0]
        if (nchunks > 1) {
            issue_x_chunk(sb, tid, run0, 1);
            CP_COMMIT();                               // group [X1] (in flight)
        }

        for (; tile < gend; tile++) {
            const int m0 = (tile & 31) * M_TILE;
            const int pr = tile & 1;

            float d[2][8][4];
            #pragma unroll
            for (int a = 0; a < 2; a++)
                #pragma unroll
                for (int bq = 0; bq < 8; bq++)
                    #pragma unroll
                    for (int cq = 0; cq < 4; cq++) d[a][bq][cq] = 0.0f;

            #pragma unroll
            for (int kt = 0; kt < KT_PER_TILE; kt++) {
                const int c = (tile - run0) * KT_PER_TILE + kt;
                // pending groups at this point: current X(c) maybe + X(c+1)
                if (c == nchunks - 1) { CP_WAIT(0); } else { CP_WAIT(1); }
                __syncthreads();

                if (kt == 0 && tid < 256)
                    c_sm[pr * 256 + tid] = centroids[o * DIM + tid];

                if (c + 2 < nchunks) {
                    issue_x_chunk(sb, tid, run0, c + 2);
                    CP_COMMIT();
                }

                const uint32_t xbase = sb + OFF_X + (c % STAGES) * XBUFB;
                const uint32_t abase = sb + OFF_A + kt * ABUFB;

                #pragma unroll
                for (int kk = 0; kk < K_CHUNK / 16; kk++) {
                    uint32_t xf[2][4], bf[4][4];
                    #pragma unroll
                    for (int mt = 0; mt < 2; mt++) {   // X (A-operand) m16k16 frags
                        uint32_t addr = xbase
                                      + (32 * wmi + 16 * mt + (l & 15)) * ROWB
                                      + kk * 32 + (l >> 4) * 16;
                        LDMX4(xf[mt][0], xf[mt][1], xf[mt][2], xf[mt][3], addr);
                    }
                    #pragma unroll
                    for (int nt = 0; nt < 4; nt++) {   // A (B-operand) n8k16 frag pairs
                        uint32_t addr = abase
                                      + (64 * wn + 16 * nt + ((mg >> 1) << 3) + rr) * ROWB
                                      + kk * 32 + (mg & 1) * 16;
                        LDMX4(bf[nt][0], bf[nt][1], bf[nt][2], bf[nt][3], addr);
                    }
                    #pragma unroll
                    for (int mt = 0; mt < 2; mt++)
                        #pragma unroll
                        for (int n8 = 0; n8 < 8; n8++)
                            mma16816(d[mt][n8], xf[mt],
                                     bf[n8 >> 1][(n8 & 1) * 2],
                                     bf[n8 >> 1][(n8 & 1) * 2 + 1]);
                }
            }

            // ---- epilogue: y += centroid, row-squared-sum, bell membership ----
            #pragma unroll
            for (int mt = 0; mt < 2; mt++) {
                #pragma unroll
                for (int h = 0; h < 2; h++) {
                    float s = 0.0f;
                    #pragma unroll
                    for (int n8 = 0; n8 < 8; n8++) {
                        int n = 64 * wn + 8 * n8 + ((l & 3) << 1);
                        float v0 = d[mt][n8][h * 2]     + c_sm[pr * 256 + n];
                        float v1 = d[mt][n8][h * 2 + 1] + c_sm[pr * 256 + n + 1];
                        s = fmaf(v0, v0, fmaf(v1, v1, s));
                    }
                    s += __shfl_xor_sync(0xffffffffu, s, 1);
                    s += __shfl_xor_sync(0xffffffffu, s, 2);
                    if ((l & 3) == 0)
                        part[(32 * wmi + 16 * mt + 8 * h + (l >> 2)) * 4 + wn] = s;
                }
            }
            __syncthreads();

            if (tid < 128) {
                float acc = part[tid * 4] + part[tid * 4 + 1]
                          + part[tid * 4 + 2] + part[tid * 4 + 3];
                float bb = __ldg(bvec + o);
                float p = exp2f(bb * log2f(acc));   // (rx^2)^b = rx^(2b)
                out[(size_t)(m0 + tid) * ORULE + o] = 1.0f / (1.0f + p);
            }
            __syncthreads();   // 'part' reuse ordering for next tile
        }
    }
}

// -------------------- launch --------------------
extern "C" void kernel_launch(void* const* d_in, const int* in_sizes, int n_in,
                              void* d_out, int out_size) {
    (void)in_sizes; (void)n_in; (void)out_size;
    const float* x         = (const float*)d_in[0];   // [4096,256]
    const float* scales    = (const float*)d_in[1];   // [256,256]
    const float* rots      = (const float*)d_in[2];   // [256,256,256]
    const float* centroids = (const float*)d_in[3];   // [256,256,1]
    const float* bvec      = (const float*)d_in[4];   // [256]
    float* out = (float*)d_out;                       // [4096,256]

    cudaFuncSetAttribute(fuzzy_bell_kernel,
                         cudaFuncAttributeMaxDynamicSharedMemorySize, SMEM_TOTAL);

    build_x_kernel<<<BATCH, 256>>>(x);
    build_A_kernel<<<dim3(36, ORULE), dim3(32, 32)>>>(scales, rots);
    fuzzy_bell_kernel<<<GRID, THREADS, SMEM_TOTAL>>>(centroids, bvec, out);
}

// round 14
// speedup vs baseline: 1.5414x; 1.0670x over previous
#include <cuda_runtime.h>
#include <cuda_fp16.h>
#include <cstdint>

#define DEV __device__ __forceinline__

// -------------------- problem sizes --------------------
static constexpr int BATCH = 4096;
static constexpr int ORULE = 256;
static constexpr int DIM   = 256;

static constexpr int M_TILE  = 128;                // batch rows per tile
static constexpr int K_CHUNK = 64;                 // K slice per X pipeline stage
static constexpr int KT_PER_TILE = DIM / K_CHUNK;  // 4
static constexpr int STAGES  = 3;                  // X ring stages
static constexpr int THREADS = 512;                // 16 warps, 4 per SMSP
static constexpr int NTILES  = (BATCH / M_TILE) * ORULE;  // 8192, o-major
static constexpr int NSM     = 148;
static constexpr int TILES_PER_CTA = (NTILES + NSM - 1) / NSM;  // 56
static constexpr int GRID    = (NTILES + TILES_PER_CTA - 1) / TILES_PER_CTA;

// -------------------- smem layout --------------------
// rows padded to 72 halves (144B): conflict-free ldmatrix (R9-verified)
static constexpr int ROWB   = 144;
static constexpr int XBUFB  = M_TILE * ROWB;       // 18432: one X stage
static constexpr int ABUFB  = DIM * ROWB;          // 36864: one A K-chunk
static constexpr int OFF_X  = 0;                   // 3 stages -> 55296
static constexpr int OFF_A  = STAGES * XBUFB;      // 55296; 4 chunks -> 147456
static constexpr int OFF_C  = OFF_A + KT_PER_TILE * ABUFB;  // 202752: c_sm[256]
static constexpr int OFF_P  = OFF_C + 1024;                 // 203776: 128x4 floats
static constexpr int SMEM_TOTAL = OFF_P + 2048;             // 205824

// -------------------- scratch (device globals; no allocation) --------------------
__device__ __align__(16) __half g_Af[(size_t)ORULE * DIM * DIM];  // 33.5 MB
__device__ __align__(16) __half g_xf[(size_t)BATCH * DIM];        // 2 MB

// -------------------- PTX helpers (sm_80-era, compile at compute_103) ----------
DEV uint32_t smem_to_u32(const void* p) {
    uint32_t a;
    asm("{ .reg .u64 t; cvta.to.shared.u64 t, %1; cvt.u32.u64 %0, t; }" : "=r"(a) : "l"(p));
    return a;
}

DEV void cp_async16(uint32_t saddr, const void* g) {
    asm volatile("cp.async.cg.shared.global [%0], [%1], 16;" :: "r"(saddr), "l"(g));
}
#define CP_COMMIT() asm volatile("cp.async.commit_group;" ::: "memory")
#define CP_WAIT(n)  asm volatile("cp.async.wait_group %0;" :: "n"(n) : "memory")

#define LDMX4(r0, r1, r2, r3, addr) \
    asm volatile("ldmatrix.sync.aligned.m8n8.x4.shared.b16 {%0,%1,%2,%3}, [%4];" \
                 : "=r"(r0), "=r"(r1), "=r"(r2), "=r"(r3) : "r"(addr))

DEV void mma16816(float* d, const uint32_t* a, uint32_t b0, uint32_t b1) {
    asm volatile(
        "mma.sync.aligned.m16n8k16.row.col.f32.f16.f16.f32 "
        "{%0,%1,%2,%3}, {%4,%5,%6,%7}, {%8,%9}, {%0,%1,%2,%3};"
        : "+f"(d[0]), "+f"(d[1]), "+f"(d[2]), "+f"(d[3])
        : "r"(a[0]), "r"(a[1]), "r"(a[2]), "r"(a[3]), "r"(b0), "r"(b1));
}

// ---- fused prepass: grid (37, 256), 256 threads ----
// bx<36: one 32x32 tile-pair (bi<=bj) of A[o]; vectorized 16B loads/stores,
//        smem-staged so the mirrored (transposed) tile also stores 16B rows.
// bx==36: fp32->fp16 convert of x slice [o*16 .. o*16+16) rows, 16B I/O.
__global__ void build_all_kernel(const float* __restrict__ x,
                                 const float* __restrict__ scales,
                                 const float* __restrict__ rots) {
    const int o  = blockIdx.y;
    const int bx = blockIdx.x;
    const int t  = threadIdx.x;

    if (bx == 36) {   // ---- x convert: 4096 floats per block ----
        const float* xs = x + (size_t)o * 4096;
        __half* xd = g_xf + (size_t)o * 4096;
        #pragma unroll
        for (int it = 0; it < 4; it++) {
            int idx = it * 1024 + t * 4;
            float4 v = *reinterpret_cast<const float4*>(xs + idx);
            __half2 h0 = __floats2half2_rn(v.x, v.y);
            __half2 h1 = __floats2half2_rn(v.z, v.w);
            *reinterpret_cast<__half2*>(xd + idx)     = h0;
            *reinterpret_cast<__half2*>(xd + idx + 2) = h1;
        }
        return;
    }

    __shared__ float Us[32][33];
    int tt = bx, bi = 0;
    while (tt >= 8 - bi) { tt -= 8 - bi; bi++; }
    const int bj = bi + tt;
    const size_t base = (size_t)o * DIM * DIM;

    {   // load 32x32 tile of rots (upper source), 4 floats per thread
        int r = t >> 3, c4 = (t & 7) * 4;
        float4 v = *reinterpret_cast<const float4*>(
            rots + base + (size_t)(bi * 32 + r) * DIM + bj * 32 + c4);
        Us[r][c4] = v.x; Us[r][c4 + 1] = v.y; Us[r][c4 + 2] = v.z; Us[r][c4 + 3] = v.w;
    }
    __syncthreads();

    if (t < 128) {   // upper tile: A[bi*32+r][bj*32+c] (diag handling if bi==bj)
        int r = t >> 2, c8 = (t & 3) * 8;
        __half hv[8];
        if (bi == bj) {
            float sc = scales[o * DIM + bi * 32 + r];
            #pragma unroll
            for (int cc = 0; cc < 8; cc++) {
                int c = c8 + cc;
                float val = (c == r) ? sc : (c > r ? Us[r][c] : Us[c][r]);
                hv[cc] = __float2half(val);
            }
        } else {
            #pragma unroll
            for (int cc = 0; cc < 8; cc++) hv[cc] = __float2half(Us[r][c8 + cc]);
        }
        *reinterpret_cast<uint4*>(g_Af + base + (size_t)(bi * 32 + r) * DIM
                                  + bj * 32 + c8) = *reinterpret_cast<uint4*>(hv);
    } else if (bi != bj) {   // mirror tile: A[bj*32+r][bi*32+c] = Us[c][r]
        int t2 = t - 128;
        int r = t2 >> 2, c8 = (t2 & 3) * 8;
        __half hv[8];
        #pragma unroll
        for (int cc = 0; cc < 8; cc++) hv[cc] = __float2half(Us[c8 + cc][r]);
        *reinterpret_cast<uint4*>(g_Af + base + (size_t)(bj * 32 + r) * DIM
                                  + bi * 32 + c8) = *reinterpret_cast<uint4*>(hv);
    }
}

// -------------------- loaders --------------------
// X chunk c (counted within the current o-run): tile = run_tile0 + c/4, kt = c%4
DEV void issue_x_chunk(uint32_t sb, int tid, int run_tile0, int c) {
    const int tile = run_tile0 + (c >> 2);
    const int kt   = c & 3;
    const int mi   = tile & 31;
    const __half* Xb = g_xf + (((size_t)mi * M_TILE) << 8) + kt * K_CHUNK;
    const uint32_t base = sb + OFF_X + (c % STAGES) * XBUFB;
    #pragma unroll
    for (int i = tid; i < 1024; i += THREADS) {      // 128 rows x 64 halves
        int row = i >> 3, seg = i & 7;
        cp_async16(base + row * ROWB + seg * 16,
                   Xb + ((size_t)row << 8) + seg * 8);
    }
}

// full A[o]: 4 K-chunks, 256 rows x 64 halves each
DEV void issue_A(uint32_t sb, int tid, int o) {
    const __half* Ao = g_Af + ((size_t)o << 16);
    #pragma unroll
    for (int kt = 0; kt < KT_PER_TILE; kt++) {
        const uint32_t base = sb + OFF_A + kt * ABUFB;
        const __half* Ab = Ao + kt * K_CHUNK;
        for (int i = tid; i < 2048; i += THREADS) {
            int row = i >> 3, seg = i & 7;
            cp_async16(base + row * ROWB + seg * 16,
                       Ab + ((size_t)row << 8) + seg * 8);
        }
    }
}

// -------------------- main kernel: persistent, A smem-resident per o-run ------------
__global__ void __launch_bounds__(THREADS, 1)
fuzzy_bell_kernel(const float* __restrict__ centroids,
                  const float* __restrict__ bvec,
                  float* __restrict__ out) {
    extern __shared__ char smem[];
    const uint32_t sb = smem_to_u32(smem);
    const int tid = threadIdx.x;
    const int wid = tid >> 5;
    const int l   = tid & 31;

    const int t_start = blockIdx.x * TILES_PER_CTA;
    if (t_start >= NTILES) return;
    const int t_end = min(t_start + TILES_PER_CTA, NTILES);

    const int wmi = wid >> 2;   // 0..3: M group (32 rows)
    const int wn  = wid & 3;    // 0..3: N quarter (64 cols)
    const int mg  = l >> 3, rr = l & 7;

    float* c_sm = reinterpret_cast<float*>(smem + OFF_C);   // [256]
    float* part = reinterpret_cast<float*>(smem + OFF_P);

    int tile = t_start;
    while (tile < t_end) {
        const int o    = tile >> 5;
        const int gend = min(t_end, (o + 1) << 5);   // end of this o-run
        const int run0 = tile;
        const int nchunks = (gend - run0) * KT_PER_TILE;
        const float bb = __ldg(bvec + o);

        // ---- o-boundary: drain ring, load A[o] + centroid + prologue X ----
        CP_WAIT(0);
        __syncthreads();            // all reads of previous A/X finished
        if (tid < 256) c_sm[tid] = centroids[o * DIM + tid];
        issue_A(sb, tid, o);
        CP_COMMIT();                                   // group [A]
        issue_x_chunk(sb, tid, run0, 0);
        CP_COMMIT();                                   // group [X0]
        if (nchunks > 1) {
            issue_x_chunk(sb, tid, run0, 1);
            CP_COMMIT();                               // group [X1] (in flight)
        }

        for (; tile < gend; tile++) {
            const int m0 = (tile & 31) * M_TILE;

            float d[2][8][4];
            #pragma unroll
            for (int a = 0; a < 2; a++)
                #pragma unroll
                for (int bq = 0; bq < 8; bq++)
                    #pragma unroll
                    for (int cq = 0; cq < 4; cq++) d[a][bq][cq] = 0.0f;

            #pragma unroll
            for (int kt = 0; kt < KT_PER_TILE; kt++) {
                const int c = (tile - run0) * KT_PER_TILE + kt;
                if (c == nchunks - 1) { CP_WAIT(0); } else { CP_WAIT(1); }
                __syncthreads();

                if (c + 2 < nchunks) {
                    issue_x_chunk(sb, tid, run0, c + 2);
                    CP_COMMIT();
                }

                const uint32_t xbase = sb + OFF_X + (c % STAGES) * XBUFB;
                const uint32_t abase = sb + OFF_A + kt * ABUFB;

                #pragma unroll
                for (int kk = 0; kk < K_CHUNK / 16; kk++) {
                    uint32_t xf[2][4], bf[4][4];
                    #pragma unroll
                    for (int mt = 0; mt < 2; mt++) {   // X (A-operand) m16k16 frags
                        uint32_t addr = xbase
                                      + (32 * wmi + 16 * mt + (l & 15)) * ROWB
                                      + kk * 32 + (l >> 4) * 16;
                        LDMX4(xf[mt][0], xf[mt][1], xf[mt][2], xf[mt][3], addr);
                    }
                    #pragma unroll
                    for (int nt = 0; nt < 4; nt++) {   // A (B-operand) n8k16 frag pairs
                        uint32_t addr = abase
                                      + (64 * wn + 16 * nt + ((mg >> 1) << 3) + rr) * ROWB
                                      + kk * 32 + (mg & 1) * 16;
                        LDMX4(bf[nt][0], bf[nt][1], bf[nt][2], bf[nt][3], addr);
                    }
                    #pragma unroll
                    for (int mt = 0; mt < 2; mt++)
                        #pragma unroll
                        for (int n8 = 0; n8 < 8; n8++)
                            mma16816(d[mt][n8], xf[mt],
                                     bf[n8 >> 1][(n8 & 1) * 2],
                                     bf[n8 >> 1][(n8 & 1) * 2 + 1]);
                }
            }

            // ---- epilogue: y += centroid, row-squared-sum, bell membership ----
            #pragma unroll
            for (int mt = 0; mt < 2; mt++) {
                #pragma unroll
                for (int h = 0; h < 2; h++) {
                    float s = 0.0f;
                    #pragma unroll
                    for (int n8 = 0; n8 < 8; n8++) {
                        int n = 64 * wn + 8 * n8 + ((l & 3) << 1);
                        float v0 = d[mt][n8][h * 2]     + c_sm[n];
                        float v1 = d[mt][n8][h * 2 + 1] + c_sm[n + 1];
                        s = fmaf(v0, v0, fmaf(v1, v1, s));
                    }
                    s += __shfl_xor_sync(0xffffffffu, s, 1);
                    s += __shfl_xor_sync(0xffffffffu, s, 2);
                    if ((l & 3) == 0)
                        part[(32 * wmi + 16 * mt + 8 * h + (l >> 2)) * 4 + wn] = s;
                }
            }
            __syncthreads();

            if (tid < 128) {
                float acc = part[tid * 4] + part[tid * 4 + 1]
                          + part[tid * 4 + 2] + part[tid * 4 + 3];
                float p = exp2f(bb * log2f(acc));   // (rx^2)^b = rx^(2b)
                out[(size_t)(m0 + tid) * ORULE + o] = 1.0f / (1.0f + p);
            }
            // no trailing sync: next tile's chunk-boundary sync (or o-boundary
            // sync) orders the next 'part' write after these reads
        }
    }
}

// -------------------- launch --------------------
extern "C" void kernel_launch(void* const* d_in, const int* in_sizes, int n_in,
                              void* d_out, int out_size) {
    (void)in_sizes; (void)n_in; (void)out_size;
    const float* x         = (const float*)d_in[0];   // [4096,256]
    const float* scales    = (const float*)d_in[1];   // [256,256]
    const float* rots      = (const float*)d_in[2];   // [256,256,256]
    const float* centroids = (const float*)d_in[3];   // [256,256,1]
    const float* bvec      = (const float*)d_in[4];   // [256]
    float* out = (float*)d_out;                       // [4096,256]

    cudaFuncSetAttribute(fuzzy_bell_kernel,
                         cudaFuncAttributeMaxDynamicSharedMemorySize, SMEM_TOTAL);

    build_all_kernel<<<dim3(37, ORULE), 256>>>(x, scales, rots);
    fuzzy_bell_kernel<<<GRID, THREADS, SMEM_TOTAL>>>(centroids, bvec, out);
}

// round 15
// speedup vs baseline: 1.7454x; 1.1323x over previous
#include <cuda_runtime.h>
#include <cuda_fp16.h>
#include <cstdint>

#define DEV __device__ __forceinline__

// -------------------- problem sizes --------------------
static constexpr int BATCH = 4096;
static constexpr int ORULE = 256;
static constexpr int DIM   = 256;

static constexpr int M_TILE  = 128;                // batch rows per tile
static constexpr int K_CHUNK = 64;                 // K slice per X pipeline stage
static constexpr int KT_PER_TILE = DIM / K_CHUNK;  // 4
static constexpr int STAGES  = 3;                  // X ring stages
static constexpr int THREADS = 512;                // 16 warps, 4 per SMSP
static constexpr int NTILES  = (BATCH / M_TILE) * ORULE;  // 8192, o-major
static constexpr int NSM     = 148;
static constexpr int TILES_PER_CTA = (NTILES + NSM - 1) / NSM;  // 56
static constexpr int GRID    = (NTILES + TILES_PER_CTA - 1) / TILES_PER_CTA;

// -------------------- smem layout --------------------
// rows padded to 72 halves (144B): conflict-free ldmatrix (R9-verified)
static constexpr int ROWB   = 144;
static constexpr int XBUFB  = M_TILE * ROWB;       // 18432: one X stage
static constexpr int ABUFB  = DIM * ROWB;          // 36864: one A K-chunk
static constexpr int OFF_X  = 0;                   // 3 stages -> 55296
static constexpr int OFF_A  = STAGES * XBUFB;      // 55296; 4 chunks -> 147456
static constexpr int OFF_C  = OFF_A + KT_PER_TILE * ABUFB;  // 202752: c_sm[256]
static constexpr int OFF_P  = OFF_C + 1024;                 // 203776: 128x4 floats
static constexpr int SMEM_TOTAL = OFF_P + 2048;             // 205824

// -------------------- scratch (device globals; no allocation) --------------------
__device__ __align__(16) __half g_Af[(size_t)ORULE * DIM * DIM];  // 33.5 MB
__device__ __align__(16) __half g_xf[(size_t)BATCH * DIM];        // 2 MB

// -------------------- PTX helpers (sm_80-era, compile at compute_103) ----------
DEV uint32_t smem_to_u32(const void* p) {
    uint32_t a;
    asm("{ .reg .u64 t; cvta.to.shared.u64 t, %1; cvt.u32.u64 %0, t; }" : "=r"(a) : "l"(p));
    return a;
}

DEV void cp_async16(uint32_t saddr, const void* g) {
    asm volatile("cp.async.cg.shared.global [%0], [%1], 16;" :: "r"(saddr), "l"(g));
}
#define CP_COMMIT() asm volatile("cp.async.commit_group;" ::: "memory")
#define CP_WAIT(n)  asm volatile("cp.async.wait_group %0;" :: "n"(n) : "memory")

// named-barrier sync over one wmi group (4 warps, 128 threads); membar for members
#define BAR_GRP(id) asm volatile("bar.sync %0, 128;" :: "r"(id) : "memory")

#define LDMX4(r0, r1, r2, r3, addr) \
    asm volatile("ldmatrix.sync.aligned.m8n8.x4.shared.b16 {%0,%1,%2,%3}, [%4];" \
                 : "=r"(r0), "=r"(r1), "=r"(r2), "=r"(r3) : "r"(addr))

DEV void mma16816(float* d, const uint32_t* a, uint32_t b0, uint32_t b1) {
    asm volatile(
        "mma.sync.aligned.m16n8k16.row.col.f32.f16.f16.f32 "
        "{%0,%1,%2,%3}, {%4,%5,%6,%7}, {%8,%9}, {%0,%1,%2,%3};"
        : "+f"(d[0]), "+f"(d[1]), "+f"(d[2]), "+f"(d[3])
        : "r"(a[0]), "r"(a[1]), "r"(a[2]), "r"(a[3]), "r"(b0), "r"(b1));
}

// ---- fused prepass: grid (37, 256), 256 threads (R14-verified) ----
__global__ void build_all_kernel(const float* __restrict__ x,
                                 const float* __restrict__ scales,
                                 const float* __restrict__ rots) {
    const int o  = blockIdx.y;
    const int bx = blockIdx.x;
    const int t  = threadIdx.x;

    if (bx == 36) {   // ---- x convert: 4096 floats per block ----
        const float* xs = x + (size_t)o * 4096;
        __half* xd = g_xf + (size_t)o * 4096;
        #pragma unroll
        for (int it = 0; it < 4; it++) {
            int idx = it * 1024 + t * 4;
            float4 v = *reinterpret_cast<const float4*>(xs + idx);
            __half2 h0 = __floats2half2_rn(v.x, v.y);
            __half2 h1 = __floats2half2_rn(v.z, v.w);
            *reinterpret_cast<__half2*>(xd + idx)     = h0;
            *reinterpret_cast<__half2*>(xd + idx + 2) = h1;
        }
        return;
    }

    __shared__ float Us[32][33];
    int tt = bx, bi = 0;
    while (tt >= 8 - bi) { tt -= 8 - bi; bi++; }
    const int bj = bi + tt;
    const size_t base = (size_t)o * DIM * DIM;

    {   // load 32x32 tile of rots (upper source), 4 floats per thread
        int r = t >> 3, c4 = (t & 7) * 4;
        float4 v = *reinterpret_cast<const float4*>(
            rots + base + (size_t)(bi * 32 + r) * DIM + bj * 32 + c4);
        Us[r][c4] = v.x; Us[r][c4 + 1] = v.y; Us[r][c4 + 2] = v.z; Us[r][c4 + 3] = v.w;
    }
    __syncthreads();

    if (t < 128) {   // upper tile: A[bi*32+r][bj*32+c] (diag handling if bi==bj)
        int r = t >> 2, c8 = (t & 3) * 8;
        __half hv[8];
        if (bi == bj) {
            float sc = scales[o * DIM + bi * 32 + r];
            #pragma unroll
            for (int cc = 0; cc < 8; cc++) {
                int c = c8 + cc;
                float val = (c == r) ? sc : (c > r ? Us[r][c] : Us[c][r]);
                hv[cc] = __float2half(val);
            }
        } else {
            #pragma unroll
            for (int cc = 0; cc < 8; cc++) hv[cc] = __float2half(Us[r][c8 + cc]);
        }
        *reinterpret_cast<uint4*>(g_Af + base + (size_t)(bi * 32 + r) * DIM
                                  + bj * 32 + c8) = *reinterpret_cast<uint4*>(hv);
    } else if (bi != bj) {   // mirror tile: A[bj*32+r][bi*32+c] = Us[c][r]
        int t2 = t - 128;
        int r = t2 >> 2, c8 = (t2 & 3) * 8;
        __half hv[8];
        #pragma unroll
        for (int cc = 0; cc < 8; cc++) hv[cc] = __float2half(Us[c8 + cc][r]);
        *reinterpret_cast<uint4*>(g_Af + base + (size_t)(bj * 32 + r) * DIM
                                  + bi * 32 + c8) = *reinterpret_cast<uint4*>(hv);
    }
}

// -------------------- loaders --------------------
// per-GROUP X chunk: group wmi loads its own 32 rows of chunk c (2 cp.async/thread)
DEV void issue_x_group(uint32_t sb, int wmi, int tig, int run0, int c) {
    const int tile = run0 + (c >> 2);
    const int kt   = c & 3;
    const int mi   = tile & 31;
    const __half* Xb = g_xf + (((size_t)(mi * M_TILE + 32 * wmi)) << 8) + kt * K_CHUNK;
    const uint32_t base = sb + OFF_X + (c % STAGES) * XBUFB + (32 * wmi) * ROWB;
    #pragma unroll
    for (int i = tig; i < 256; i += 128) {      // 32 rows x 8 segs of 16B
        int row = i >> 3, seg = i & 7;
        cp_async16(base + row * ROWB + seg * 16,
                   Xb + ((size_t)row << 8) + seg * 8);
    }
}

// full A[o]: cooperative (all 512 threads), 4 K-chunks, 256 rows x 64 halves each
DEV void issue_A(uint32_t sb, int tid, int o) {
    const __half* Ao = g_Af + ((size_t)o << 16);
    #pragma unroll
    for (int kt = 0; kt < KT_PER_TILE; kt++) {
        const uint32_t base = sb + OFF_A + kt * ABUFB;
        const __half* Ab = Ao + kt * K_CHUNK;
        for (int i = tid; i < 2048; i += THREADS) {
            int row = i >> 3, seg = i & 7;
            cp_async16(base + row * ROWB + seg * 16,
                       Ab + ((size_t)row << 8) + seg * 8);
        }
    }
}

// -------------------- main kernel: persistent, group-local synchronization ----------
__global__ void __launch_bounds__(THREADS, 1)
fuzzy_bell_kernel(const float* __restrict__ centroids,
                  const float* __restrict__ bvec,
                  float* __restrict__ out) {
    extern __shared__ char smem[];
    const uint32_t sb = smem_to_u32(smem);
    const int tid = threadIdx.x;
    const int wid = tid >> 5;
    const int l   = tid & 31;

    const int t_start = blockIdx.x * TILES_PER_CTA;
    if (t_start >= NTILES) return;
    const int t_end = min(t_start + TILES_PER_CTA, NTILES);

    const int wmi  = wid >> 2;   // 0..3: M group (32 rows) — barrier domain
    const int wn   = wid & 3;    // 0..3: N quarter (64 cols)
    const int tig  = tid & 127;  // thread index within group
    const int barid = wmi + 1;   // named barrier id 1..4
    const int mg  = l >> 3, rr = l & 7;

    float* c_sm = reinterpret_cast<float*>(smem + OFF_C);   // [256]
    float* part = reinterpret_cast<float*>(smem + OFF_P);   // [128][4]

    int tile = t_start;
    while (tile < t_end) {
        const int o    = tile >> 5;
        const int gend = min(t_end, (o + 1) << 5);   // end of this o-run
        const int run0 = tile;
        const int nchunks = (gend - run0) * KT_PER_TILE;
        const float bb = __ldg(bvec + o);

        // ---- o-boundary: drain, full sync, load A[o] + centroid + prologue X ----
        CP_WAIT(0);
        __syncthreads();            // all reads of previous A/X finished, all groups
        if (tid < 256) c_sm[tid] = centroids[o * DIM + tid];
        issue_A(sb, tid, o);
        CP_COMMIT();                                   // group [A]
        issue_x_group(sb, wmi, tig, run0, 0);
        CP_COMMIT();                                   // group [X0]
        if (nchunks > 1) {
            issue_x_group(sb, wmi, tig, run0, 1);
            CP_COMMIT();                               // group [X1] (in flight)
        }

        for (; tile < gend; tile++) {
            const int m0 = (tile & 31) * M_TILE;

            float d[2][8][4];
            #pragma unroll
            for (int a = 0; a < 2; a++)
                #pragma unroll
                for (int bq = 0; bq < 8; bq++)
                    #pragma unroll
                    for (int cq = 0; cq < 4; cq++) d[a][bq][cq] = 0.0f;

            #pragma unroll
            for (int kt = 0; kt < KT_PER_TILE; kt++) {
                const int c = (tile - run0) * KT_PER_TILE + kt;
                if (c == nchunks - 1) { CP_WAIT(0); } else { CP_WAIT(1); }
                // chunk 0: full sync publishes cooperative A + c_sm;
                // otherwise group-local barrier (X slice is group-private)
                if (c == 0) { __syncthreads(); } else { BAR_GRP(barid); }

                if (c + 2 < nchunks) {
                    issue_x_group(sb, wmi, tig, run0, c + 2);
                    CP_COMMIT();
                }

                const uint32_t xbase = sb + OFF_X + (c % STAGES) * XBUFB;
                const uint32_t abase = sb + OFF_A + kt * ABUFB;

                #pragma unroll
                for (int kk = 0; kk < K_CHUNK / 16; kk++) {
                    uint32_t xf[2][4], bf[4][4];
                    #pragma unroll
                    for (int mt = 0; mt < 2; mt++) {   // X (A-operand) m16k16 frags
                        uint32_t addr = xbase
                                      + (32 * wmi + 16 * mt + (l & 15)) * ROWB
                                      + kk * 32 + (l >> 4) * 16;
                        LDMX4(xf[mt][0], xf[mt][1], xf[mt][2], xf[mt][3], addr);
                    }
                    #pragma unroll
                    for (int nt = 0; nt < 4; nt++) {   // A (B-operand) n8k16 frag pairs
                        uint32_t addr = abase
                                      + (64 * wn + 16 * nt + ((mg >> 1) << 3) + rr) * ROWB
                                      + kk * 32 + (mg & 1) * 16;
                        LDMX4(bf[nt][0], bf[nt][1], bf[nt][2], bf[nt][3], addr);
                    }
                    #pragma unroll
                    for (int mt = 0; mt < 2; mt++)
                        #pragma unroll
                        for (int n8 = 0; n8 < 8; n8++)
                            mma16816(d[mt][n8], xf[mt],
                                     bf[n8 >> 1][(n8 & 1) * 2],
                                     bf[n8 >> 1][(n8 & 1) * 2 + 1]);
                }
            }

            // ---- epilogue (group-local): y += centroid, norm, bell membership ----
            #pragma unroll
            for (int mt = 0; mt < 2; mt++) {
                #pragma unroll
                for (int h = 0; h < 2; h++) {
                    float s = 0.0f;
                    #pragma unroll
                    for (int n8 = 0; n8 < 8; n8++) {
                        int n = 64 * wn + 8 * n8 + ((l & 3) << 1);
                        float v0 = d[mt][n8][h * 2]     + c_sm[n];
                        float v1 = d[mt][n8][h * 2 + 1] + c_sm[n + 1];
                        s = fmaf(v0, v0, fmaf(v1, v1, s));
                    }
                    s += __shfl_xor_sync(0xffffffffu, s, 1);
                    s += __shfl_xor_sync(0xffffffffu, s, 2);
                    if ((l & 3) == 0)
                        part[(32 * wmi + 16 * mt + 8 * h + (l >> 2)) * 4 + wn] = s;
                }
            }
            BAR_GRP(barid);   // publish part within group

            if (wn == 0) {    // group's first warp finalizes its 32 rows
                int r = 32 * wmi + l;
                float acc = part[r * 4] + part[r * 4 + 1]
                          + part[r * 4 + 2] + part[r * 4 + 3];
                float p = exp2f(bb * log2f(acc));   // (rx^2)^b = rx^(2b)
                out[(size_t)(m0 + r) * ORULE + o] = 1.0f / (1.0f + p);
            }
            // part reuse at tile+1 is ordered by tile+1's chunk group barriers
        }
    }
}

// -------------------- launch --------------------
extern "C" void kernel_launch(void* const* d_in, const int* in_sizes, int n_in,
                              void* d_out, int out_size) {
    (void)in_sizes; (void)n_in; (void)out_size;
    const float* x         = (const float*)d_in[0];   // [4096,256]
    const float* scales    = (const float*)d_in[1];   // [256,256]
    const float* rots      = (const float*)d_in[2];   // [256,256,256]
    const float* centroids = (const float*)d_in[3];   // [256,256,1]
    const float* bvec      = (const float*)d_in[4];   // [256]
    float* out = (float*)d_out;                       // [4096,256]

    cudaFuncSetAttribute(fuzzy_bell_kernel,
                         cudaFuncAttributeMaxDynamicSharedMemorySize, SMEM_TOTAL);

    build_all_kernel<<<dim3(37, ORULE), 256>>>(x, scales, rots);
    fuzzy_bell_kernel<<<GRID, THREADS, SMEM_TOTAL>>>(centroids, bvec, out);
}

// round 16
// speedup vs baseline: 1.7839x; 1.0221x over previous
#include <cuda_runtime.h>
#include <cuda_fp16.h>
#include <cstdint>

#define DEV __device__ __forceinline__

// -------------------- problem sizes --------------------
static constexpr int BATCH = 4096;
static constexpr int ORULE = 256;
static constexpr int DIM   = 256;

static constexpr int M_TILE  = 128;                // batch rows per tile
static constexpr int K_CHUNK = 64;                 // K slice per X buffer
static constexpr int KT_PER_TILE = DIM / K_CHUNK;  // 4
static constexpr int THREADS = 512;                // 16 warps, 4 per SMSP
static constexpr int NTILES  = (BATCH / M_TILE) * ORULE;  // 8192, o-major
static constexpr int NSM     = 148;
static constexpr int TILES_PER_CTA = (NTILES + NSM - 1) / NSM;  // 56
static constexpr int GRID    = (NTILES + TILES_PER_CTA - 1) / TILES_PER_CTA;

// -------------------- smem layout --------------------
// rows padded to 72 halves (144B): conflict-free ldmatrix (R9-verified)
static constexpr int ROWB   = 144;
static constexpr int XBUFB  = M_TILE * ROWB;       // 18432: one X chunk buffer
static constexpr int ABUFB  = DIM * ROWB;          // 36864: one A K-chunk
static constexpr int OFF_X  = 0;                   // 4 ring buffers -> 73728
static constexpr int OFF_A  = 4 * XBUFB;           // 73728; 4 chunks -> 221184
static constexpr int OFF_C  = OFF_A + KT_PER_TILE * ABUFB;  // 221184: c_sm[256]
static constexpr int OFF_P  = OFF_C + 1024;                 // 222208: 128x4 floats
static constexpr int SMEM_TOTAL = OFF_P + 2048;             // 224256

// -------------------- scratch (device globals; no allocation) --------------------
__device__ __align__(16) __half g_Af[(size_t)ORULE * DIM * DIM];  // 33.5 MB
__device__ __align__(16) __half g_xf[(size_t)BATCH * DIM];        // 2 MB

// -------------------- PTX helpers (sm_80-era, compile at compute_103) ----------
DEV uint32_t smem_to_u32(const void* p) {
    uint32_t a;
    asm("{ .reg .u64 t; cvta.to.shared.u64 t, %1; cvt.u32.u64 %0, t; }" : "=r"(a) : "l"(p));
    return a;
}

DEV void cp_async16(uint32_t saddr, const void* g) {
    asm volatile("cp.async.cg.shared.global [%0], [%1], 16;" :: "r"(saddr), "l"(g));
}
#define CP_COMMIT() asm volatile("cp.async.commit_group;" ::: "memory")
#define CP_WAIT(n)  asm volatile("cp.async.wait_group %0;" :: "n"(n) : "memory")

// named-barrier sync over one wmi group (4 warps, 128 threads)
#define BAR_GRP(id) asm volatile("bar.sync %0, 128;" :: "r"(id) : "memory")

#define LDMX4(r0, r1, r2, r3, addr) \
    asm volatile("ldmatrix.sync.aligned.m8n8.x4.shared.b16 {%0,%1,%2,%3}, [%4];" \
                 : "=r"(r0), "=r"(r1), "=r"(r2), "=r"(r3) : "r"(addr))

DEV void mma16816(float* d, const uint32_t* a, uint32_t b0, uint32_t b1) {
    asm volatile(
        "mma.sync.aligned.m16n8k16.row.col.f32.f16.f16.f32 "
        "{%0,%1,%2,%3}, {%4,%5,%6,%7}, {%8,%9}, {%0,%1,%2,%3};"
        : "+f"(d[0]), "+f"(d[1]), "+f"(d[2]), "+f"(d[3])
        : "r"(a[0]), "r"(a[1]), "r"(a[2]), "r"(a[3]), "r"(b0), "r"(b1));
}

// ---- fused prepass: grid (37, 256), 256 threads (R14-verified) ----
__global__ void build_all_kernel(const float* __restrict__ x,
                                 const float* __restrict__ scales,
                                 const float* __restrict__ rots) {
    const int o  = blockIdx.y;
    const int bx = blockIdx.x;
    const int t  = threadIdx.x;

    if (bx == 36) {   // ---- x convert: 4096 floats per block ----
        const float* xs = x + (size_t)o * 4096;
        __half* xd = g_xf + (size_t)o * 4096;
        #pragma unroll
        for (int it = 0; it < 4; it++) {
            int idx = it * 1024 + t * 4;
            float4 v = *reinterpret_cast<const float4*>(xs + idx);
            __half2 h0 = __floats2half2_rn(v.x, v.y);
            __half2 h1 = __floats2half2_rn(v.z, v.w);
            *reinterpret_cast<__half2*>(xd + idx)     = h0;
            *reinterpret_cast<__half2*>(xd + idx + 2) = h1;
        }
        return;
    }

    __shared__ float Us[32][33];
    int tt = bx, bi = 0;
    while (tt >= 8 - bi) { tt -= 8 - bi; bi++; }
    const int bj = bi + tt;
    const size_t base = (size_t)o * DIM * DIM;

    {   // load 32x32 tile of rots (upper source), 4 floats per thread
        int r = t >> 3, c4 = (t & 7) * 4;
        float4 v = *reinterpret_cast<const float4*>(
            rots + base + (size_t)(bi * 32 + r) * DIM + bj * 32 + c4);
        Us[r][c4] = v.x; Us[r][c4 + 1] = v.y; Us[r][c4 + 2] = v.z; Us[r][c4 + 3] = v.w;
    }
    __syncthreads();

    if (t < 128) {   // upper tile: A[bi*32+r][bj*32+c] (diag handling if bi==bj)
        int r = t >> 2, c8 = (t & 3) * 8;
        __half hv[8];
        if (bi == bj) {
            float sc = scales[o * DIM + bi * 32 + r];
            #pragma unroll
            for (int cc = 0; cc < 8; cc++) {
                int c = c8 + cc;
                float val = (c == r) ? sc : (c > r ? Us[r][c] : Us[c][r]);
                hv[cc] = __float2half(val);
            }
        } else {
            #pragma unroll
            for (int cc = 0; cc < 8; cc++) hv[cc] = __float2half(Us[r][c8 + cc]);
        }
        *reinterpret_cast<uint4*>(g_Af + base + (size_t)(bi * 32 + r) * DIM
                                  + bj * 32 + c8) = *reinterpret_cast<uint4*>(hv);
    } else if (bi != bj) {   // mirror tile: A[bj*32+r][bi*32+c] = Us[c][r]
        int t2 = t - 128;
        int r = t2 >> 2, c8 = (t2 & 3) * 8;
        __half hv[8];
        #pragma unroll
        for (int cc = 0; cc < 8; cc++) hv[cc] = __float2half(Us[c8 + cc][r]);
        *reinterpret_cast<uint4*>(g_Af + base + (size_t)(bj * 32 + r) * DIM
                                  + bi * 32 + c8) = *reinterpret_cast<uint4*>(hv);
    }
}

// -------------------- loaders --------------------
// per-GROUP X pair: group wmi loads its 32-row slice of chunks c and c+1
DEV void issue_x_pair(uint32_t sb, int wmi, int tig, int run0, int c) {
    #pragma unroll
    for (int j = 0; j < 2; j++) {
        const int cc   = c + j;
        const int tile = run0 + (cc >> 2);
        const int kt   = cc & 3;
        const int mi   = tile & 31;
        const __half* Xb = g_xf + (((size_t)(mi * M_TILE + 32 * wmi)) << 8)
                         + kt * K_CHUNK;
        const uint32_t base = sb + OFF_X + (cc & 3) * XBUFB + (32 * wmi) * ROWB;
        #pragma unroll
        for (int i = tig; i < 256; i += 128) {      // 32 rows x 8 segs of 16B
            int row = i >> 3, seg = i & 7;
            cp_async16(base + row * ROWB + seg * 16,
                       Xb + ((size_t)row << 8) + seg * 8);
        }
    }
}

// full A[o]: cooperative (all 512 threads), 4 K-chunks, 256 rows x 64 halves each
DEV void issue_A(uint32_t sb, int tid, int o) {
    const __half* Ao = g_Af + ((size_t)o << 16);
    #pragma unroll
    for (int kt = 0; kt < KT_PER_TILE; kt++) {
        const uint32_t base = sb + OFF_A + kt * ABUFB;
        const __half* Ab = Ao + kt * K_CHUNK;
        for (int i = tid; i < 2048; i += THREADS) {
            int row = i >> 3, seg = i & 7;
            cp_async16(base + row * ROWB + seg * 16,
                       Ab + ((size_t)row << 8) + seg * 8);
        }
    }
}

// load one kk's B-operand fragment set (4x LDMX4 from resident A region)
DEV void load_bf_set(uint32_t* bf, uint32_t abase, int wn, int mg, int rr, int kk) {
    #pragma unroll
    for (int nt = 0; nt < 4; nt++) {
        uint32_t addr = abase + (64 * wn + 16 * nt + ((mg >> 1) << 3) + rr) * ROWB
                      + kk * 32 + (mg & 1) * 16;
        LDMX4(bf[nt * 4 + 0], bf[nt * 4 + 1], bf[nt * 4 + 2], bf[nt * 4 + 3], addr);
    }
}

// -------------------- main kernel: persistent, paired chunks, bf preload ------------
__global__ void __launch_bounds__(THREADS, 1)
fuzzy_bell_kernel(const float* __restrict__ centroids,
                  const float* __restrict__ bvec,
                  float* __restrict__ out) {
    extern __shared__ char smem[];
    const uint32_t sb = smem_to_u32(smem);
    const int tid = threadIdx.x;
    const int wid = tid >> 5;
    const int l   = tid & 31;

    const int t_start = blockIdx.x * TILES_PER_CTA;
    if (t_start >= NTILES) return;
    const int t_end = min(t_start + TILES_PER_CTA, NTILES);

    const int wmi  = wid >> 2;   // 0..3: M group (32 rows) — barrier domain
    const int wn   = wid & 3;    // 0..3: N quarter (64 cols)
    const int tig  = tid & 127;  // thread index within group
    const int barid = wmi + 1;   // named barrier id 1..4 (0 is __syncthreads)
    const int mg  = l >> 3, rr = l & 7;

    float* c_sm = reinterpret_cast<float*>(smem + OFF_C);   // [256]
    float* part = reinterpret_cast<float*>(smem + OFF_P);   // [128][4]

    int tile = t_start;
    while (tile < t_end) {
        const int o    = tile >> 5;
        const int gend = min(t_end, (o + 1) << 5);   // end of this o-run
        const int run0 = tile;
        const int nchunks = (gend - run0) * KT_PER_TILE;
        const float bb = __ldg(bvec + o);

        // ---- o-boundary: drain, full sync, load A[o] + centroid + X pair(0,1) ----
        CP_WAIT(0);
        __syncthreads();            // all reads of previous A/X finished, all groups
        if (tid < 256) c_sm[tid] = centroids[o * DIM + tid];
        issue_A(sb, tid, o);
        CP_COMMIT();                                   // group [A]
        issue_x_pair(sb, wmi, tig, run0, 0);
        CP_COMMIT();                                   // group [X0,X1]

        for (; tile < gend; tile++) {
            const int m0 = (tile & 31) * M_TILE;

            float d[2][8][4];
            #pragma unroll
            for (int a = 0; a < 2; a++)
                #pragma unroll
                for (int bq = 0; bq < 8; bq++)
                    #pragma unroll
                    for (int cq = 0; cq < 4; cq++) d[a][bq][cq] = 0.0f;

            #pragma unroll
            for (int kt = 0; kt < KT_PER_TILE; kt++) {
                const int c = (tile - run0) * KT_PER_TILE + kt;
                const uint32_t abase = sb + OFF_A + kt * ABUFB;

                uint32_t bf0[16];           // kk=0 B-fragments
                bool preloaded = false;

                if ((kt & 1) == 0) {        // pair boundary: wait + barrier
                    if (c > 0) {            // A resident & synced -> safe pre-barrier
                        load_bf_set(bf0, abase, wn, mg, rr, 0);
                        preloaded = true;
                    }
                    CP_WAIT(0);             // completes the pair covering chunks c,c+1
                    if (c == 0) { __syncthreads(); } else { BAR_GRP(barid); }
                    if (c + 2 < nchunks) {  // prefetch next pair (may cross tiles)
                        issue_x_pair(sb, wmi, tig, run0, c + 2);
                        CP_COMMIT();
                    }
                }
                if (!preloaded) load_bf_set(bf0, abase, wn, mg, rr, 0);

                const uint32_t xbase = sb + OFF_X + (c & 3) * XBUFB;

                #pragma unroll
                for (int kk = 0; kk < K_CHUNK / 16; kk++) {
                    uint32_t xf[2][4];
                    uint32_t bfl[16];
                    const uint32_t* bfu;
                    if (kk == 0) {
                        bfu = bf0;
                    } else {
                        load_bf_set(bfl, abase, wn, mg, rr, kk);
                        bfu = bfl;
                    }
                    #pragma unroll
                    for (int mt = 0; mt < 2; mt++) {   // X (A-operand) m16k16 frags
                        uint32_t addr = xbase
                                      + (32 * wmi + 16 * mt + (l & 15)) * ROWB
                                      + kk * 32 + (l >> 4) * 16;
                        LDMX4(xf[mt][0], xf[mt][1], xf[mt][2], xf[mt][3], addr);
                    }
                    #pragma unroll
                    for (int mt = 0; mt < 2; mt++)
                        #pragma unroll
                        for (int n8 = 0; n8 < 8; n8++)
                            mma16816(d[mt][n8], xf[mt],
                                     bfu[(n8 >> 1) * 4 + (n8 & 1) * 2],
                                     bfu[(n8 >> 1) * 4 + (n8 & 1) * 2 + 1]);
                }
            }

            // ---- epilogue (group-local): y += centroid, norm, bell membership ----
            #pragma unroll
            for (int mt = 0; mt < 2; mt++) {
                #pragma unroll
                for (int h = 0; h < 2; h++) {
                    float s = 0.0f;
                    #pragma unroll
                    for (int n8 = 0; n8 < 8; n8++) {
                        int n = 64 * wn + 8 * n8 + ((l & 3) << 1);
                        float v0 = d[mt][n8][h * 2]     + c_sm[n];
                        float v1 = d[mt][n8][h * 2 + 1] + c_sm[n + 1];
                        s = fmaf(v0, v0, fmaf(v1, v1, s));
                    }
                    s += __shfl_xor_sync(0xffffffffu, s, 1);
                    s += __shfl_xor_sync(0xffffffffu, s, 2);
                    if ((l & 3) == 0)
                        part[(32 * wmi + 16 * mt + 8 * h + (l >> 2)) * 4 + wn] = s;
                }
            }
            BAR_GRP(barid);   // publish part within group

            if (wn == 0) {    // group's first warp finalizes its 32 rows
                int r = 32 * wmi + l;
                float acc = part[r * 4] + part[r * 4 + 1]
                          + part[r * 4 + 2] + part[r * 4 + 3];
                float p = exp2f(bb * log2f(acc));   // (rx^2)^b = rx^(2b)
                out[(size_t)(m0 + r) * ORULE + o] = 1.0f / (1.0f + p);
            }
            // part reuse at tile+1 is ordered by tile+1's pair-boundary barriers
        }
    }
}

// -------------------- launch --------------------
extern "C" void kernel_launch(void* const* d_in, const int* in_sizes, int n_in,
                              void* d_out, int out_size) {
    (void)in_sizes; (void)n_in; (void)out_size;
    const float* x         = (const float*)d_in[0];   // [4096,256]
    const float* scales    = (const float*)d_in[1];   // [256,256]
    const float* rots      = (const float*)d_in[2];   // [256,256,256]
    const float* centroids = (const float*)d_in[3];   // [256,256,1]
    const float* bvec      = (const float*)d_in[4];   // [256]
    float* out = (float*)d_out;                       // [4096,256]

    cudaFuncSetAttribute(fuzzy_bell_kernel,
                         cudaFuncAttributeMaxDynamicSharedMemorySize, SMEM_TOTAL);

    build_all_kernel<<<dim3(37, ORULE), 256>>>(x, scales, rots);
    fuzzy_bell_kernel<<<GRID, THREADS, SMEM_TOTAL>>>(centroids, bvec, out);
}